// round 7
// baseline (speedup 1.0000x reference)
#include <cuda_runtime.h>
#include <stdint.h>

// Fused projection + greedy per-pixel NMS. Output dtype is FLOAT32.
//   coords_grid: [N, M, 3, H, W] f32,  anchor_P: [N, 3, 4] f32
//   out: [N, H, W, 8] f32 (indices as floats)
// 2 pixels per thread: warp w owns 64 consecutive pixels; lane handles
// p0 = w*64+lane and p1 = p0+32 -> both streams perfectly coalesced, and the
// two independent NMS chains interleave for 2x ILP (kernel is latency-bound:
// R6 ncu showed issue=52%, all pipes < 30%).
#define TOPK 8

// One candidate step for one pixel's register-resident NMS state.
#define CAND_STEP(cm, q00,q01,q02,q03,q10,q11,q12,q13,q20,q21,q22,q23, SX,SY,SI,CNT,MIDX) \
  do {                                                                        \
    const float cx = (cm)[0];                                                 \
    const float cy = (cm)[plane];                                             \
    const float cz = (cm)[2 * plane];                                         \
    const float X0 = fmaf(q00, cx, fmaf(q01, cy, fmaf(q02, cz, q03)));        \
    const float X1 = fmaf(q10, cx, fmaf(q11, cy, fmaf(q12, cz, q13)));        \
    const float X2 = fmaf(q20, cx, fmaf(q21, cy, fmaf(q22, cz, q23)));        \
    const float zc = fmaxf(X2, 1e-6f);                                        \
    const float iv = 1.0f / zc;                                               \
    const float x  = X0 * iv;                                                 \
    const float y  = X1 * iv;                                                 \
    float d2[TOPK];                                                           \
    _Pragma("unroll")                                                         \
    for (int k = 0; k < TOPK; k++) {                                          \
      const float dx = SX[k] - x;                                             \
      const float dy = SY[k] - y;                                             \
      d2[k] = fmaf(dx, dx, dy * dy);                                          \
    }                                                                         \
    const float m01 = fminf(d2[0], d2[1]);                                    \
    const float m23 = fminf(d2[2], d2[3]);                                    \
    const float m45 = fminf(d2[4], d2[5]);                                    \
    const float m67 = fminf(d2[6], d2[7]);                                    \
    const float dmin = fminf(fminf(m01, m23), fminf(m45, m67));               \
    if ((dmin > 4.0f) && (CNT < TOPK)) {                                      \
      _Pragma("unroll")                                                       \
      for (int k = 0; k < TOPK; k++) {                                        \
        if (CNT == k) { SX[k] = x; SY[k] = y; SI[k] = (MIDX); }               \
      }                                                                       \
      CNT++;                                                                  \
    }                                                                         \
  } while (0)

template <bool VEC_STORE>
__global__ __launch_bounds__(256)
void nms_coords_kernel(const float* __restrict__ coords,
                       const float* __restrict__ P,
                       float* __restrict__ out,
                       int HW, int M, long long total)
{
    const int       lane = threadIdx.x & 31;
    const long long gw   = (long long)blockIdx.x * 8 + (threadIdx.x >> 5);
    const long long p0   = gw * 64 + lane;
    const long long p1   = p0 + 32;
    const bool a0 = (p0 < total);
    const bool a1 = (p1 < total);
    const long long q0 = a0 ? p0 : 0;    // inactive lanes read pixel 0 (valid),
    const long long q1 = a1 ? p1 : 0;    // results discarded; keeps ballots safe

    const long long plane   = HW;
    const long long mstride = 3 * plane;

    const int n0 = (int)(q0 / HW);
    const int n1 = (int)(q1 / HW);

    const float* Pa = P + n0 * 12;
    const float a00=Pa[0],a01=Pa[1],a02=Pa[2], a03=Pa[3];
    const float a10=Pa[4],a11=Pa[5],a12=Pa[6], a13=Pa[7];
    const float a20=Pa[8],a21=Pa[9],a22=Pa[10],a23=Pa[11];
    const float* Pb = P + n1 * 12;
    const float b00=Pb[0],b01=Pb[1],b02=Pb[2], b03=Pb[3];
    const float b10=Pb[4],b11=Pb[5],b12=Pb[6], b13=Pb[7];
    const float b20=Pb[8],b21=Pb[9],b22=Pb[10],b23=Pb[11];

    const float* cm0 = coords + (long long)n0 * M * mstride + (q0 - (long long)n0 * HW);
    const float* cm1 = coords + (long long)n1 * M * mstride + (q1 - (long long)n1 * HW);

    float sx0[TOPK], sy0[TOPK], sx1[TOPK], sy1[TOPK];
    int   si0[TOPK], si1[TOPK];
#pragma unroll
    for (int k = 0; k < TOPK; k++) {
        sx0[k] = 1e9f; sy0[k] = 1e9f; si0[k] = 0;
        sx1[k] = 1e9f; sy1[k] = 1e9f; si1[k] = 0;
    }
    int cnt0 = a0 ? 0 : TOPK;            // inactive pixels vote "done"
    int cnt1 = a1 ? 0 : TOPK;

    // Main loop: both pixels per iteration (interleaved independent chains).
    bool done0 = false, done1 = false;
    int m = 0;
    for (; m < M; m++) {
        CAND_STEP(cm0, a00,a01,a02,a03,a10,a11,a12,a13,a20,a21,a22,a23,
                  sx0, sy0, si0, cnt0, m);
        CAND_STEP(cm1, b00,b01,b02,b03,b10,b11,b12,b13,b20,b21,b22,b23,
                  sx1, sy1, si1, cnt1, m);
        cm0 += mstride; cm1 += mstride;
        done0 = __all_sync(0xffffffffu, cnt0 >= TOPK);
        done1 = __all_sync(0xffffffffu, cnt1 >= TOPK);
        if (done0 | done1) { m++; break; }
    }
    // Tail: at most one pixel still needs candidates; don't drag the other.
    if (done0 && !done1) {
        for (; m < M; m++) {
            CAND_STEP(cm1, b00,b01,b02,b03,b10,b11,b12,b13,b20,b21,b22,b23,
                      sx1, sy1, si1, cnt1, m);
            cm1 += mstride;
            if (__all_sync(0xffffffffu, cnt1 >= TOPK)) break;
        }
    } else if (done1 && !done0) {
        for (; m < M; m++) {
            CAND_STEP(cm0, a00,a01,a02,a03,a10,a11,a12,a13,a20,a21,a22,a23,
                      sx0, sy0, si0, cnt0, m);
            cm0 += mstride;
            if (__all_sync(0xffffffffu, cnt0 >= TOPK)) break;
        }
    }

    // Output as FLOAT32 (indices exactly representable).
    if (VEC_STORE) {
        if (a0) {
            float4* o = reinterpret_cast<float4*>(out) + p0 * 2;
            o[0] = make_float4((float)si0[0], (float)si0[1], (float)si0[2], (float)si0[3]);
            o[1] = make_float4((float)si0[4], (float)si0[5], (float)si0[6], (float)si0[7]);
        }
        if (a1) {
            float4* o = reinterpret_cast<float4*>(out) + p1 * 2;
            o[0] = make_float4((float)si1[0], (float)si1[1], (float)si1[2], (float)si1[3]);
            o[1] = make_float4((float)si1[4], (float)si1[5], (float)si1[6], (float)si1[7]);
        }
    } else {
        if (a0) {
            float* o = out + p0 * TOPK;
#pragma unroll
            for (int k = 0; k < TOPK; k++) o[k] = (float)si0[k];
        }
        if (a1) {
            float* o = out + p1 * TOPK;
#pragma unroll
            for (int k = 0; k < TOPK; k++) o[k] = (float)si1[k];
        }
    }
}

extern "C" void kernel_launch(void* const* d_in, const int* in_sizes, int n_in,
                              void* d_out, int out_size)
{
    // coords = largest input, P = smallest (robust to metadata ordering).
    int ci = 0, pi = 0;
    for (int i = 1; i < n_in; i++) {
        if (in_sizes[i] > in_sizes[ci]) ci = i;
        if (in_sizes[i] < in_sizes[pi]) pi = i;
    }
    const float* coords = (const float*)d_in[ci];
    const float* P      = (const float*)d_in[pi];
    float* out          = (float*)d_out;

    // Runtime shapes: N = P/12, HW = out/(8N), M = coords/(3·N·HW)
    const long long p_elems      = in_sizes[pi];
    const long long coords_elems = in_sizes[ci];
    const int N  = (int)(p_elems / 12);
    const int HW = (int)(out_size / (TOPK * (long long)N));
    const int M  = (int)(coords_elems / (3LL * N * HW));
    const long long total = (long long)N * HW;

    const long long numWarps = (total + 63) / 64;     // 64 pixels per warp
    const int blocks = (int)((numWarps + 7) / 8);     // 8 warps per block

    if ((((uintptr_t)d_out) & 15u) == 0) {
        nms_coords_kernel<true><<<blocks, 256>>>(coords, P, out, HW, M, total);
    } else {
        nms_coords_kernel<false><<<blocks, 256>>>(coords, P, out, HW, M, total);
    }
}

// round 8
// speedup vs baseline: 1.1825x; 1.1825x over previous
#include <cuda_runtime.h>
#include <stdint.h>

// Fused projection + greedy per-pixel NMS. Output dtype is FLOAT32.
//   coords_grid: [N, M, 3, H, W] f32,  anchor_P: [N, 3, 4] f32
//   out: [N, H, W, 8] f32 (indices as floats)
//
// R6 design (1 pixel/thread, 57 regs, occ ~42%) + software prefetch of the
// next candidate's 3 loads (hides the long_scoreboard stall that bounded R6),
// single reciprocal, balanced min tree. R7's 2-px/thread variant is reverted:
// it halved occupancy (94 regs) and regressed.
#define TOPK 8

template <bool VEC_STORE>
__global__ __launch_bounds__(256)
void nms_coords_kernel(const float* __restrict__ coords,
                       const float* __restrict__ P,
                       float* __restrict__ out,
                       int HW, int M, int total)
{
    const int tid = blockIdx.x * 256 + threadIdx.x;
    const bool act = (tid < total);
    const int t   = act ? tid : 0;        // inactive lanes shadow pixel 0
    const int n   = t / HW;
    const int pix = t - n * HW;

    // Camera matrix for this image (12 floats, L2-broadcast)
    const float* Pn = P + n * 12;
    const float p00 = Pn[0], p01 = Pn[1], p02 = Pn[2],  p03 = Pn[3];
    const float p10 = Pn[4], p11 = Pn[5], p12 = Pn[6],  p13 = Pn[7];
    const float p20 = Pn[8], p21 = Pn[9], p22 = Pn[10], p23 = Pn[11];

    const long long plane   = HW;         // stride between c-components
    const long long mstride = 3 * plane;  // stride between candidates
    const float* cm = coords + (long long)n * M * mstride + pix;

    // Register-resident NMS state (constant indices after unroll -> registers)
    float sx[TOPK], sy[TOPK];
    int   si[TOPK];
#pragma unroll
    for (int k = 0; k < TOPK; k++) { sx[k] = 1e9f; sy[k] = 1e9f; si[k] = 0; }
    int cnt = act ? 0 : TOPK;             // inactive lanes vote "done"

    // Prime the pipeline: candidate 0's loads.
    float cx = cm[0];
    float cy = cm[plane];
    float cz = cm[2 * plane];

    for (int m = 0; m < M; m++) {
        // Prefetch candidate m+1 (independent of NMS state -> the compiler
        // hoists these LDGs a full iteration ahead of their use).
        const float* nxt = cm + mstride;
        const float* pf  = (m + 1 < M) ? nxt : cm;   // clamp: no OOB on last
        const float nx = pf[0];
        const float ny = pf[plane];
        const float nz = pf[2 * plane];

        // Projection of candidate m: X = P[:, :3] @ c + P[:, 3]
        const float X0 = fmaf(p00, cx, fmaf(p01, cy, fmaf(p02, cz, p03)));
        const float X1 = fmaf(p10, cx, fmaf(p11, cy, fmaf(p12, cz, p13)));
        const float X2 = fmaf(p20, cx, fmaf(p21, cy, fmaf(p22, cz, p23)));
        const float z  = fmaxf(X2, 1e-6f);
        const float iv = 1.0f / z;
        const float x  = X0 * iv;
        const float y  = X1 * iv;

        // Suppression: min squared distance over all 8 slots (balanced tree).
        // Unfilled slots hold 1e9 -> d2 ~ 2e18, never suppresses (matches ref).
        float d2[TOPK];
#pragma unroll
        for (int k = 0; k < TOPK; k++) {
            const float dx = sx[k] - x;
            const float dy = sy[k] - y;
            d2[k] = fmaf(dx, dx, dy * dy);
        }
        const float m01 = fminf(d2[0], d2[1]);
        const float m23 = fminf(d2[2], d2[3]);
        const float m45 = fminf(d2[4], d2[5]);
        const float m67 = fminf(d2[6], d2[7]);
        const float dmin = fminf(fminf(m01, m23), fminf(m45, m67));

        const bool keep = (dmin > 4.0f) && (cnt < TOPK);
        if (keep) {
#pragma unroll
            for (int k = 0; k < TOPK; k++) {
                if (cnt == k) { sx[k] = x; sy[k] = y; si[k] = m; }
            }
            cnt++;
        }

        // Rotate prefetch registers, advance pointer.
        cx = nx; cy = ny; cz = nz; cm = nxt;

        // Warp early exit: once every lane kept 8, the rest are no-ops
        // (reference's keep requires cnt < topk, so trailing m's can't write).
        if (__all_sync(0xffffffffu, cnt >= TOPK)) break;
    }

    if (!act) return;

    // Output as FLOAT32 (indices exactly representable).
    if (VEC_STORE) {
        float4* o = reinterpret_cast<float4*>(out) + (long long)tid * 2;
        o[0] = make_float4((float)si[0], (float)si[1], (float)si[2], (float)si[3]);
        o[1] = make_float4((float)si[4], (float)si[5], (float)si[6], (float)si[7]);
    } else {
        float* o = out + (long long)tid * TOPK;
#pragma unroll
        for (int k = 0; k < TOPK; k++) o[k] = (float)si[k];
    }
}

extern "C" void kernel_launch(void* const* d_in, const int* in_sizes, int n_in,
                              void* d_out, int out_size)
{
    // coords = largest input, P = smallest (robust to metadata ordering).
    int ci = 0, pi = 0;
    for (int i = 1; i < n_in; i++) {
        if (in_sizes[i] > in_sizes[ci]) ci = i;
        if (in_sizes[i] < in_sizes[pi]) pi = i;
    }
    const float* coords = (const float*)d_in[ci];
    const float* P      = (const float*)d_in[pi];
    float* out          = (float*)d_out;

    // Runtime shapes: N = P/12, HW = out/(8N), M = coords/(3·N·HW)
    const long long p_elems      = in_sizes[pi];
    const long long coords_elems = in_sizes[ci];
    const int N  = (int)(p_elems / 12);
    const int HW = (int)(out_size / (TOPK * (long long)N));
    const int M  = (int)(coords_elems / (3LL * N * HW));
    const int total = N * HW;

    const int blocks = (total + 255) / 256;

    if ((((uintptr_t)d_out) & 15u) == 0) {
        nms_coords_kernel<true><<<blocks, 256>>>(coords, P, out, HW, M, total);
    } else {
        nms_coords_kernel<false><<<blocks, 256>>>(coords, P, out, HW, M, total);
    }
}

// round 9
// speedup vs baseline: 1.3266x; 1.1218x over previous
#include <cuda_runtime.h>
#include <stdint.h>

// Fused projection + greedy per-pixel NMS. Output dtype is FLOAT32.
//   coords_grid: [N, M, 3, H, W] f32,  anchor_P: [N, 3, 4] f32
//   out: [N, H, W, 8] f32 (indices as floats)
//
// R8 (depth-1 prefetch) left ~100cyc/iter of DRAM latency exposed
// (8 warps/SMSP x ~60cyc/iter = 480 < 577). Depth-2 pipeline covers ~960cyc.
// __launch_bounds__(256,4) pins the 4-blocks/SM occupancy class (<=64 regs).
#define TOPK 8

template <bool VEC_STORE>
__global__ __launch_bounds__(256, 4)
void nms_coords_kernel(const float* __restrict__ coords,
                       const float* __restrict__ P,
                       float* __restrict__ out,
                       int HW, int M, int total)
{
    const int tid = blockIdx.x * 256 + threadIdx.x;
    const bool act = (tid < total);
    const int t   = act ? tid : 0;        // inactive lanes shadow pixel 0
    const int n   = t / HW;
    const int pix = t - n * HW;

    // Camera matrix for this image (12 floats, L2-broadcast)
    const float* Pn = P + n * 12;
    const float p00 = Pn[0], p01 = Pn[1], p02 = Pn[2],  p03 = Pn[3];
    const float p10 = Pn[4], p11 = Pn[5], p12 = Pn[6],  p13 = Pn[7];
    const float p20 = Pn[8], p21 = Pn[9], p22 = Pn[10], p23 = Pn[11];

    const long long plane   = HW;
    const long long mstride = 3 * plane;
    const float* base  = coords + (long long)n * M * mstride + pix;
    const float* lastp = base + (long long)(M - 1) * mstride;  // clamp target

    // Register-resident NMS state
    float sx[TOPK], sy[TOPK];
    int   si[TOPK];
#pragma unroll
    for (int k = 0; k < TOPK; k++) { sx[k] = 1e9f; sy[k] = 1e9f; si[k] = 0; }

    // ---- Peel m = 0: always kept (slots are 1e9 sentinels, cnt==0). ----
    {
        const float cx = base[0];
        const float cy = base[plane];
        const float cz = base[2 * plane];
        const float X0 = fmaf(p00, cx, fmaf(p01, cy, fmaf(p02, cz, p03)));
        const float X1 = fmaf(p10, cx, fmaf(p11, cy, fmaf(p12, cz, p13)));
        const float X2 = fmaf(p20, cx, fmaf(p21, cy, fmaf(p22, cz, p23)));
        const float z  = fmaxf(X2, 1e-6f);
        const float iv = 1.0f / z;
        sx[0] = X0 * iv; sy[0] = X1 * iv; si[0] = 0;
    }
    int cnt = act ? 1 : TOPK;             // inactive lanes vote "done"

    // ---- Depth-2 software pipeline over m = 1..M-1 ----
    const float* s1 = (base + mstride)     < lastp ? (base + mstride)     : lastp;
    const float* s2 = (base + 2 * mstride) < lastp ? (base + 2 * mstride) : lastp;
    float cx0 = s1[0], cy0 = s1[plane], cz0 = s1[2 * plane];   // stage m
    float cx1 = s2[0], cy1 = s2[plane], cz1 = s2[2 * plane];   // stage m+1
    const float* pf = base + 3 * mstride;                      // stage m+2

    for (int m = 1; m < M; m++) {
        // Prefetch candidate m+2 (clamped; independent of NMS state).
        const float* q = pf < lastp ? pf : lastp;
        const float nx = q[0];
        const float ny = q[plane];
        const float nz = q[2 * plane];

        // Projection of candidate m
        const float X0 = fmaf(p00, cx0, fmaf(p01, cy0, fmaf(p02, cz0, p03)));
        const float X1 = fmaf(p10, cx0, fmaf(p11, cy0, fmaf(p12, cz0, p13)));
        const float X2 = fmaf(p20, cx0, fmaf(p21, cy0, fmaf(p22, cz0, p23)));
        const float z  = fmaxf(X2, 1e-6f);
        const float iv = 1.0f / z;
        const float x  = X0 * iv;
        const float y  = X1 * iv;

        // Suppression: min squared distance over all 8 slots (balanced tree).
        float d2[TOPK];
#pragma unroll
        for (int k = 0; k < TOPK; k++) {
            const float dx = sx[k] - x;
            const float dy = sy[k] - y;
            d2[k] = fmaf(dx, dx, dy * dy);
        }
        const float m01 = fminf(d2[0], d2[1]);
        const float m23 = fminf(d2[2], d2[3]);
        const float m45 = fminf(d2[4], d2[5]);
        const float m67 = fminf(d2[6], d2[7]);
        const float dmin = fminf(fminf(m01, m23), fminf(m45, m67));

        const bool keep = (dmin > 4.0f) && (cnt < TOPK);
        if (keep) {
#pragma unroll
            for (int k = 1; k < TOPK; k++) {     // slot 0 taken by m=0 peel
                if (cnt == k) { sx[k] = x; sy[k] = y; si[k] = m; }
            }
            cnt++;
        }

        // Rotate pipeline stages.
        cx0 = cx1; cy0 = cy1; cz0 = cz1;
        cx1 = nx;  cy1 = ny;  cz1 = nz;
        pf += mstride;

        // Warp early exit: once every lane kept 8, trailing m's are no-ops.
        if (__all_sync(0xffffffffu, cnt >= TOPK)) break;
    }

    if (!act) return;

    // Output as FLOAT32 (indices exactly representable).
    if (VEC_STORE) {
        float4* o = reinterpret_cast<float4*>(out) + (long long)tid * 2;
        o[0] = make_float4((float)si[0], (float)si[1], (float)si[2], (float)si[3]);
        o[1] = make_float4((float)si[4], (float)si[5], (float)si[6], (float)si[7]);
    } else {
        float* o = out + (long long)tid * TOPK;
#pragma unroll
        for (int k = 0; k < TOPK; k++) o[k] = (float)si[k];
    }
}

extern "C" void kernel_launch(void* const* d_in, const int* in_sizes, int n_in,
                              void* d_out, int out_size)
{
    // coords = largest input, P = smallest (robust to metadata ordering).
    int ci = 0, pi = 0;
    for (int i = 1; i < n_in; i++) {
        if (in_sizes[i] > in_sizes[ci]) ci = i;
        if (in_sizes[i] < in_sizes[pi]) pi = i;
    }
    const float* coords = (const float*)d_in[ci];
    const float* P      = (const float*)d_in[pi];
    float* out          = (float*)d_out;

    // Runtime shapes: N = P/12, HW = out/(8N), M = coords/(3·N·HW)
    const long long p_elems      = in_sizes[pi];
    const long long coords_elems = in_sizes[ci];
    const int N  = (int)(p_elems / 12);
    const int HW = (int)(out_size / (TOPK * (long long)N));
    const int M  = (int)(coords_elems / (3LL * N * HW));
    const int total = N * HW;

    const int blocks = (total + 255) / 256;

    if ((((uintptr_t)d_out) & 15u) == 0) {
        nms_coords_kernel<true><<<blocks, 256>>>(coords, P, out, HW, M, total);
    } else {
        nms_coords_kernel<false><<<blocks, 256>>>(coords, P, out, HW, M, total);
    }
}